// round 10
// baseline (speedup 1.0000x reference)
#include <cuda_runtime.h>

#define NU_F 0.5f
#define HH 1024
#define WW 1024
#define ROWS 4           // output rows per thread (1024/4 = 256 blocks in y)
#define TPB 256          // threads per block; TPB*4 == WW

__global__ __launch_bounds__(TPB, 3)
void AI4Burgers_38096359915612_kernel(const float* __restrict__ u,
                                      const float* __restrict__ uvel,
                                      const float* __restrict__ w1,
                                      const float* __restrict__ w2,
                                      const float* __restrict__ w3,
                                      float* __restrict__ out)
{
    __shared__ float swA[9];   // NU * w1
    __shared__ float swB[9];   // w2 + w3
    const int tx = threadIdx.x;
    if (tx < 9) {
        swA[tx] = NU_F * __ldg(&w1[tx]);
        swB[tx] = __ldg(&w2[tx]) + __ldg(&w3[tx]);
    }
    __syncthreads();

    float A[9], Bw[9];
#pragma unroll
    for (int i = 0; i < 9; i++) { A[i] = swA[i]; Bw[i] = swB[i]; }

    const int lane = tx & 31;
    const int x0 = tx << 2;                    // 4 outputs per thread in x
    const int y0 = blockIdx.y * ROWS;          // ROWS output rows per thread
    const long base = (long)blockIdx.z * (long)(HH * WW);
    const float* __restrict__ up = u + base;
    const float* __restrict__ vp = uvel + base;
    float* __restrict__ op = out + base;

    const bool leftEdge  = (x0 == 0);          // only tx==0 (block spans full row)
    const bool rightEdge = (x0 + 4 >= WW);     // only tx==255

    // ---- FRONT-BATCHED LOADS: 10 independent LDG.128 issued before any use ----
    // 6 u rows (y0-1 .. y0+4, clamped) + 4 uvel rows (y0 .. y0+3).
    float4 urow[6];
#pragma unroll
    for (int k = 0; k < 6; k++) {
        int gy = y0 - 1 + k;
        gy = gy < 0 ? 0 : (gy > HH - 1 ? HH - 1 : gy);
        urow[k] = *reinterpret_cast<const float4*>(up + (long)gy * WW + x0);
    }
    float4 vrow[ROWS];
#pragma unroll
    for (int j = 0; j < ROWS; j++) {
        vrow[j] = *reinterpret_cast<const float4*>(vp + (long)(y0 + j) * WW + x0);
    }

    // ---- Halos via warp shuffle (per u row); boundary lanes fall back to L2-hit LDG ----
    float lft[6], rgt[6];
#pragma unroll
    for (int k = 0; k < 6; k++) {
        lft[k] = __shfl_up_sync(0xffffffffu, urow[k].w, 1);
        rgt[k] = __shfl_down_sync(0xffffffffu, urow[k].x, 1);
    }
    if (lane == 0) {
#pragma unroll
        for (int k = 0; k < 6; k++) {
            int gy = y0 - 1 + k;
            gy = gy < 0 ? 0 : (gy > HH - 1 ? HH - 1 : gy);
            lft[k] = leftEdge ? urow[k].x : __ldg(up + (long)gy * WW + x0 - 1);
        }
    }
    if (lane == 31) {
#pragma unroll
        for (int k = 0; k < 6; k++) {
            int gy = y0 - 1 + k;
            gy = gy < 0 ? 0 : (gy > HH - 1 ? HH - 1 : gy);
            rgt[k] = rightEdge ? urow[k].w : __ldg(up + (long)gy * WW + x0 + 4);
        }
    }

    // ---- Compute 4 output rows from registers ----
#pragma unroll
    for (int j = 0; j < ROWS; j++) {
        // 6-wide windows for rows j, j+1, j+2 of the loaded band
        const float w0[6] = {lft[j],     urow[j].x,     urow[j].y,     urow[j].z,     urow[j].w,     rgt[j]};
        const float w1r[6] = {lft[j + 1], urow[j + 1].x, urow[j + 1].y, urow[j + 1].z, urow[j + 1].w, rgt[j + 1]};
        const float w2r[6] = {lft[j + 2], urow[j + 2].x, urow[j + 2].y, urow[j + 2].z, urow[j + 2].w, rgt[j + 2]};
        const float uva[4] = {vrow[j].x, vrow[j].y, vrow[j].z, vrow[j].w};

        float o[4];
#pragma unroll
        for (int i = 0; i < 4; i++) {
            float s1 = A[0] * w0[i];
            s1 = fmaf(A[1], w0[i + 1], s1);
            s1 = fmaf(A[2], w0[i + 2], s1);
            s1 = fmaf(A[3], w1r[i],     s1);
            s1 = fmaf(A[4], w1r[i + 1], s1);
            s1 = fmaf(A[5], w1r[i + 2], s1);
            s1 = fmaf(A[6], w2r[i],     s1);
            s1 = fmaf(A[7], w2r[i + 1], s1);
            s1 = fmaf(A[8], w2r[i + 2], s1);

            float s2 = Bw[0] * w0[i];
            s2 = fmaf(Bw[1], w0[i + 1], s2);
            s2 = fmaf(Bw[2], w0[i + 2], s2);
            s2 = fmaf(Bw[3], w1r[i],     s2);
            s2 = fmaf(Bw[4], w1r[i + 1], s2);
            s2 = fmaf(Bw[5], w1r[i + 2], s2);
            s2 = fmaf(Bw[6], w2r[i],     s2);
            s2 = fmaf(Bw[7], w2r[i + 1], s2);
            s2 = fmaf(Bw[8], w2r[i + 2], s2);

            // Lu = NU*conv1 - uvel*(conv2+conv3)  (NU folded into A)
            o[i] = fmaf(-uva[i], s2, s1);
        }

        float4 ov;
        ov.x = o[0]; ov.y = o[1]; ov.z = o[2]; ov.w = o[3];
        *reinterpret_cast<float4*>(op + (long)(y0 + j) * WW + x0) = ov;
    }
}

extern "C" void kernel_launch(void* const* d_in, const int* in_sizes, int n_in,
                              void* d_out, int out_size)
{
    const float* u    = (const float*)d_in[0];
    const float* uvel = (const float*)d_in[1];
    const float* w1   = (const float*)d_in[2];
    const float* w2   = (const float*)d_in[3];
    const float* w3   = (const float*)d_in[4];
    float* out = (float*)d_out;

    const int B = in_sizes[0] / (HH * WW);   // 16

    dim3 grid(1, HH / ROWS, B);              // (1, 256, 16)
    dim3 block(TPB, 1, 1);                   // 256 threads cover W=1024 with float4
    AI4Burgers_38096359915612_kernel<<<grid, block>>>(u, uvel, w1, w2, w3, out);
}

// round 11
// speedup vs baseline: 1.0617x; 1.0617x over previous
#include <cuda_runtime.h>

#define NU_F 0.5f
#define HH 1024
#define WW 1024
#define ROWS 4           // output rows per thread (1024/4 = 256 blocks in y)
#define TPB 256          // threads per block; TPB*4 == WW

__global__ __launch_bounds__(TPB, 7)   // cap at 36 regs -> 7 CTAs/SM (87.5% occ)
void AI4Burgers_38096359915612_kernel(const float* __restrict__ u,
                                      const float* __restrict__ uvel,
                                      const float* __restrict__ w1,
                                      const float* __restrict__ w2,
                                      const float* __restrict__ w3,
                                      float* __restrict__ out)
{
    __shared__ float swA[9];   // NU * w1
    __shared__ float swB[9];   // w2 + w3
    const int tx = threadIdx.x;
    if (tx < 9) {
        swA[tx] = NU_F * __ldg(&w1[tx]);
        swB[tx] = __ldg(&w2[tx]) + __ldg(&w3[tx]);
    }
    __syncthreads();

    float A[9], Bw[9];
#pragma unroll
    for (int i = 0; i < 9; i++) { A[i] = swA[i]; Bw[i] = swB[i]; }

    const int lane = tx & 31;
    const unsigned x0 = (unsigned)tx << 2;             // 4 outputs per thread in x
    const unsigned y0 = blockIdx.y * ROWS;             // ROWS output rows per thread
    // 32-bit offsets: each tensor is 16*1024*1024 floats = 64 MB < 4 GB
    const unsigned base = blockIdx.z * (unsigned)(HH * WW);
    const float* __restrict__ up = u + base;
    const float* __restrict__ vp = uvel + base;
    float* __restrict__ op = out + base;

    // rolling 3-row window, each row is a 6-wide register window:
    // r[0] <-> column x0-1 (clamped), r[1..4] <-> x0..x0+3, r[5] <-> x0+4 (clamped)
    float r0[6], r1[6], r2[6];

    const bool leftEdge  = (x0 == 0);          // only tx==0 (block spans full row)
    const bool rightEdge = (x0 + 4 >= WW);     // only tx==255

    // Halo via warp shuffle: r[0] is prev lane's v.w, r[5] is next lane's v.x.
    // Only the 2 warp-boundary lanes fall back to a scalar load (L1/L2 hit).
#define LOAD_ROW(dst, gy)                                                   \
    do {                                                                    \
        const float* __restrict__ row_ = up + (unsigned)(gy) * WW;          \
        float4 v_ = *reinterpret_cast<const float4*>(row_ + x0);            \
        float lft_ = __shfl_up_sync(0xffffffffu, v_.w, 1);                  \
        float rgt_ = __shfl_down_sync(0xffffffffu, v_.x, 1);                \
        if (lane == 0)  lft_ = leftEdge  ? v_.x : __ldg(row_ + x0 - 1);     \
        if (lane == 31) rgt_ = rightEdge ? v_.w : __ldg(row_ + x0 + 4);     \
        (dst)[0] = lft_;                                                    \
        (dst)[1] = v_.x; (dst)[2] = v_.y; (dst)[3] = v_.z; (dst)[4] = v_.w; \
        (dst)[5] = rgt_;                                                    \
    } while (0)

    const int gym1 = (y0 == 0) ? 0 : (int)y0 - 1;
    LOAD_ROW(r0, gym1);
    LOAD_ROW(r1, y0);

#pragma unroll
    for (int j = 0; j < ROWS; j++) {
        const unsigned y = y0 + (unsigned)j;
        const unsigned gyp = (y + 1 < HH) ? (y + 1) : (HH - 1);
        LOAD_ROW(r2, gyp);

        float4 uvv = *reinterpret_cast<const float4*>(vp + y * WW + x0);
        const float uva[4] = {uvv.x, uvv.y, uvv.z, uvv.w};

        float o[4];
#pragma unroll
        for (int i = 0; i < 4; i++) {
            float s1 = A[0] * r0[i];
            s1 = fmaf(A[1], r0[i + 1], s1);
            s1 = fmaf(A[2], r0[i + 2], s1);
            s1 = fmaf(A[3], r1[i],     s1);
            s1 = fmaf(A[4], r1[i + 1], s1);
            s1 = fmaf(A[5], r1[i + 2], s1);
            s1 = fmaf(A[6], r2[i],     s1);
            s1 = fmaf(A[7], r2[i + 1], s1);
            s1 = fmaf(A[8], r2[i + 2], s1);

            float s2 = Bw[0] * r0[i];
            s2 = fmaf(Bw[1], r0[i + 1], s2);
            s2 = fmaf(Bw[2], r0[i + 2], s2);
            s2 = fmaf(Bw[3], r1[i],     s2);
            s2 = fmaf(Bw[4], r1[i + 1], s2);
            s2 = fmaf(Bw[5], r1[i + 2], s2);
            s2 = fmaf(Bw[6], r2[i],     s2);
            s2 = fmaf(Bw[7], r2[i + 1], s2);
            s2 = fmaf(Bw[8], r2[i + 2], s2);

            // Lu = NU*conv1 - uvel*(conv2+conv3)  (NU folded into A)
            o[i] = fmaf(-uva[i], s2, s1);
        }

        float4 ov;
        ov.x = o[0]; ov.y = o[1]; ov.z = o[2]; ov.w = o[3];
        *reinterpret_cast<float4*>(op + y * WW + x0) = ov;

        // rotate window (pure register renaming after full unroll)
#pragma unroll
        for (int k = 0; k < 6; k++) { r0[k] = r1[k]; r1[k] = r2[k]; }
    }
#undef LOAD_ROW
}

extern "C" void kernel_launch(void* const* d_in, const int* in_sizes, int n_in,
                              void* d_out, int out_size)
{
    const float* u    = (const float*)d_in[0];
    const float* uvel = (const float*)d_in[1];
    const float* w1   = (const float*)d_in[2];
    const float* w2   = (const float*)d_in[3];
    const float* w3   = (const float*)d_in[4];
    float* out = (float*)d_out;

    const int B = in_sizes[0] / (HH * WW);   // 16

    dim3 grid(1, HH / ROWS, B);              // (1, 256, 16)
    dim3 block(TPB, 1, 1);                   // 256 threads cover W=1024 with float4
    AI4Burgers_38096359915612_kernel<<<grid, block>>>(u, uvel, w1, w2, w3, out);
}

// round 12
// speedup vs baseline: 1.0737x; 1.0113x over previous
#include <cuda_runtime.h>

#define NU_F 0.5f
#define HH 1024
#define WW 1024
#define ROWS 4           // output rows per thread (1024/4 = 256 blocks in y)
#define TPB 256          // threads per block; TPB*4 == WW

__global__ __launch_bounds__(TPB)
void AI4Burgers_38096359915612_kernel(const float* __restrict__ u,
                                      const float* __restrict__ uvel,
                                      const float* __restrict__ w1,
                                      const float* __restrict__ w2,
                                      const float* __restrict__ w3,
                                      float* __restrict__ out)
{
    __shared__ float swA[9];   // NU * w1
    __shared__ float swB[9];   // w2 + w3
    const int tx = threadIdx.x;
    if (tx < 9) {
        swA[tx] = NU_F * __ldg(&w1[tx]);
        swB[tx] = __ldg(&w2[tx]) + __ldg(&w3[tx]);
    }
    __syncthreads();

    float A[9], Bw[9];
#pragma unroll
    for (int i = 0; i < 9; i++) { A[i] = swA[i]; Bw[i] = swB[i]; }

    const int lane = tx & 31;
    const unsigned x0 = (unsigned)tx << 2;           // 4 outputs per thread in x
    const unsigned y0 = blockIdx.y * ROWS;           // ROWS output rows per thread
    // 32-bit offsets: each tensor is 16*1024*1024 floats = 64 MB < 4 GB
    const unsigned base = blockIdx.z * (unsigned)(HH * WW);
    const float* __restrict__ up = u + base;
    const float* __restrict__ vp = uvel + base;
    float* __restrict__ op = out + base;

    // rolling 3-row window, each row is a 6-wide register window:
    // r[0] <-> column x0-1 (clamped), r[1..4] <-> x0..x0+3, r[5] <-> x0+4 (clamped)
    float r0[6], r1[6], r2[6];

    const bool leftEdge  = (x0 == 0);          // only tx==0 (block spans full row)
    const bool rightEdge = (x0 + 4 >= WW);     // only tx==255

    // Halo via warp shuffle: r[0] is prev lane's v.w, r[5] is next lane's v.x.
    // Only the 2 warp-boundary lanes fall back to a scalar load (L1/L2 hit).
    // u uses DEFAULT cache policy: it is the only tensor with L2 reuse (halos).
#define LOAD_ROW(dst, gy)                                                   \
    do {                                                                    \
        const float* __restrict__ row_ = up + (unsigned)(gy) * WW;          \
        float4 v_ = *reinterpret_cast<const float4*>(row_ + x0);            \
        float lft_ = __shfl_up_sync(0xffffffffu, v_.w, 1);                  \
        float rgt_ = __shfl_down_sync(0xffffffffu, v_.x, 1);                \
        if (lane == 0)  lft_ = leftEdge  ? v_.x : __ldg(row_ + x0 - 1);     \
        if (lane == 31) rgt_ = rightEdge ? v_.w : __ldg(row_ + x0 + 4);     \
        (dst)[0] = lft_;                                                    \
        (dst)[1] = v_.x; (dst)[2] = v_.y; (dst)[3] = v_.z; (dst)[4] = v_.w; \
        (dst)[5] = rgt_;                                                    \
    } while (0)

    const int gym1 = (y0 == 0) ? 0 : (int)y0 - 1;
    LOAD_ROW(r0, gym1);
    LOAD_ROW(r1, y0);

#pragma unroll
    for (int j = 0; j < ROWS; j++) {
        const unsigned y = y0 + (unsigned)j;
        const unsigned gyp = (y + 1 < HH) ? (y + 1) : (HH - 1);
        LOAD_ROW(r2, gyp);

        // uvel: read-once stream -> evict-first, keep L2 for u halos
        float4 uvv = __ldcs(reinterpret_cast<const float4*>(vp + y * WW + x0));
        const float uva[4] = {uvv.x, uvv.y, uvv.z, uvv.w};

        float o[4];
#pragma unroll
        for (int i = 0; i < 4; i++) {
            float s1 = A[0] * r0[i];
            s1 = fmaf(A[1], r0[i + 1], s1);
            s1 = fmaf(A[2], r0[i + 2], s1);
            s1 = fmaf(A[3], r1[i],     s1);
            s1 = fmaf(A[4], r1[i + 1], s1);
            s1 = fmaf(A[5], r1[i + 2], s1);
            s1 = fmaf(A[6], r2[i],     s1);
            s1 = fmaf(A[7], r2[i + 1], s1);
            s1 = fmaf(A[8], r2[i + 2], s1);

            float s2 = Bw[0] * r0[i];
            s2 = fmaf(Bw[1], r0[i + 1], s2);
            s2 = fmaf(Bw[2], r0[i + 2], s2);
            s2 = fmaf(Bw[3], r1[i],     s2);
            s2 = fmaf(Bw[4], r1[i + 1], s2);
            s2 = fmaf(Bw[5], r1[i + 2], s2);
            s2 = fmaf(Bw[6], r2[i],     s2);
            s2 = fmaf(Bw[7], r2[i + 1], s2);
            s2 = fmaf(Bw[8], r2[i + 2], s2);

            // Lu = NU*conv1 - uvel*(conv2+conv3)  (NU folded into A)
            o[i] = fmaf(-uva[i], s2, s1);
        }

        float4 ov;
        ov.x = o[0]; ov.y = o[1]; ov.z = o[2]; ov.w = o[3];
        // out: write-once stream -> evict-first store
        __stcs(reinterpret_cast<float4*>(op + y * WW + x0), ov);

        // rotate window (pure register renaming after full unroll)
#pragma unroll
        for (int k = 0; k < 6; k++) { r0[k] = r1[k]; r1[k] = r2[k]; }
    }
#undef LOAD_ROW
}

extern "C" void kernel_launch(void* const* d_in, const int* in_sizes, int n_in,
                              void* d_out, int out_size)
{
    const float* u    = (const float*)d_in[0];
    const float* uvel = (const float*)d_in[1];
    const float* w1   = (const float*)d_in[2];
    const float* w2   = (const float*)d_in[3];
    const float* w3   = (const float*)d_in[4];
    float* out = (float*)d_out;

    const int B = in_sizes[0] / (HH * WW);   // 16

    dim3 grid(1, HH / ROWS, B);              // (1, 256, 16)
    dim3 block(TPB, 1, 1);                   // 256 threads cover W=1024 with float4
    AI4Burgers_38096359915612_kernel<<<grid, block>>>(u, uvel, w1, w2, w3, out);
}